// round 14
// baseline (speedup 1.0000x reference)
#include <cuda_runtime.h>
#include <cuda_bf16.h>
#include <math.h>

// Problem shape (fixed by the dataset): input [N, T] fp32, label [N] fp32.
static constexpr int N_ROWS = 8192;
static constexpr int T_COLS = 8192;

static constexpr int THREADS = 256;              // 8 warps; warp-per-row
static constexpr int WARPS_PER_BLOCK = THREADS / 32;
static constexpr int GRID = N_ROWS / WARPS_PER_BLOCK;   // 1024 blocks
static constexpr int CHUNKS = 8;                 // 8 chunks x 8 float4 x 32 lanes = row
static constexpr int KPC = 8;                    // float4 per lane per chunk

// Scratch (no cudaMalloc). Zero at process start; RESET by the last block
// each run so graph replays are deterministic.
__device__ unsigned long long g_acc_bits;   // double accumulator, as bits
__device__ unsigned int g_ticket;

__global__ __launch_bounds__(THREADS, 3)
void loss_kernel(const float* __restrict__ in,
                 const float* __restrict__ label,
                 float* __restrict__ out) {
    const int tid  = threadIdx.x;
    const int wid  = tid >> 5;
    const int lane = tid & 31;
    const int row  = blockIdx.x * WARPS_PER_BLOCK + wid;   // one row per warp

    const size_t row_off = (size_t)row * T_COLS;
    const float4* rp = reinterpret_cast<const float4*>(in + row_off);

    // Ping-pong chunk buffers (fully unrolled -> registers).
    float4 a[KPC], b[KPC];

    // Prefetch chunk 0.
#pragma unroll
    for (int k = 0; k < KPC; k++)
        a[k] = rp[k * 32 + lane];

    float s = 0.0f;   // lane-partial sum of exp(x) over this row

#pragma unroll
    for (int ch = 0; ch < CHUNKS; ch++) {
        float4* cur = (ch & 1) ? b : a;
        float4* nxt = (ch & 1) ? a : b;

        // Issue next chunk's loads BEFORE consuming the current chunk:
        // 8 LDG.128 per lane stay in flight under the compute below.
        if (ch + 1 < CHUNKS) {
#pragma unroll
            for (int k = 0; k < KPC; k++)
                nxt[k] = rp[(ch + 1) * (KPC * 32) + k * 32 + lane];
        }

        // Chunk max consumes ALL 8 loads -> forces the front-batched wait
        // (the MLP_p1=8 pattern proven to saturate HBM).
        float c = cur[0].x;
#pragma unroll
        for (int k = 0; k < KPC; k++)
            c = fmaxf(c, fmaxf(fmaxf(cur[k].x, cur[k].y),
                               fmaxf(cur[k].z, cur[k].w)));

        // exp(c) * sum(exp(x - c)) == sum(exp(x)), exactly; |x| <~ 6 so
        // direct exp is fp32-safe (validated rel_err ~1e-7 in earlier rounds).
        float cs = 0.0f;
#pragma unroll
        for (int k = 0; k < KPC; k++) {
            cs += __expf(cur[k].x - c);
            cs += __expf(cur[k].y - c);
            cs += __expf(cur[k].z - c);
            cs += __expf(cur[k].w - c);
        }
        s = fmaf(__expf(c), cs, s);
    }

    // Warp-only reduction: no block barriers in the hot path.
#pragma unroll
    for (int off = 16; off > 0; off >>= 1)
        s += __shfl_xor_sync(0xFFFFFFFFu, s, off);

    __shared__ float s_loss[WARPS_PER_BLOCK];

    if (lane == 0) {
        const float lse = __logf(s);

        const float pos = label[row] * (float)T_COLS - 1.0f;
        const int fl = (int)floorf(pos);
        const int ce = (int)ceilf(pos);

        // Replicate reference write ORDER (later writes overwrite earlier).
        int   cols[4];
        float vals[4];
        cols[0] = max(fl - 1, 0);          vals[0] = 0.1f;
        cols[1] = fl;                      vals[1] = (fl >= 1) ? 0.4f : 0.5f;
        cols[2] = min(ce + 1, T_COLS - 1); vals[2] = 0.1f;
        cols[3] = ce;                      vals[3] = (ce < T_COLS - 1) ? 0.4f : 0.5f;

        float wsum = 0.0f, dot = 0.0f;
#pragma unroll
        for (int i = 0; i < 4; i++) {
            bool alive = true;
#pragma unroll
            for (int j = i + 1; j < 4; j++)
                if (cols[j] == cols[i]) alive = false;   // last write wins
            if (alive) {
                const float x = in[row_off + cols[i]];   // L1/L2-hot
                wsum += vals[i];
                dot  += vals[i] * x;
            }
        }
        s_loss[wid] = wsum * lse - dot;
    }

    // One barrier per BLOCK LIFETIME (not per row): combine 8 warp losses.
    __syncthreads();
    if (tid == 0) {
        double accd = 0.0;
#pragma unroll
        for (int w = 0; w < WARPS_PER_BLOCK; w++)
            accd += (double)s_loss[w];

        atomicAdd(reinterpret_cast<double*>(&g_acc_bits), accd);
        __threadfence();                          // adds visible before ticket
        const unsigned t = atomicAdd(&g_ticket, 1u);
        if (t == (unsigned)(GRID - 1)) {
            // Last block: reset state for the next graph replay, write mean.
            g_ticket = 0;
            const unsigned long long bits = atomicExch(&g_acc_bits, 0ull);
            const double total = __longlong_as_double((long long)bits);
            out[0] = (float)(total / (double)N_ROWS);
        }
    }
}

extern "C" void kernel_launch(void* const* d_in, const int* in_sizes, int n_in,
                              void* d_out, int out_size) {
    const float* input = (const float*)d_in[0];   // [N, T] fp32
    const float* label = (const float*)d_in[1];   // [N] fp32
    float* out = (float*)d_out;

    loss_kernel<<<GRID, THREADS>>>(input, label, out);
}

// round 15
// speedup vs baseline: 1.2753x; 1.2753x over previous
#include <cuda_runtime.h>
#include <cuda_bf16.h>
#include <math.h>

// Problem shape (fixed by the dataset): input [N, T] fp32, label [N] fp32.
static constexpr int N_ROWS = 8192;
static constexpr int T_COLS = 8192;

static constexpr int THREADS = 256;
static constexpr int WPB = THREADS / 32;              // 8 warps
static constexpr int VEC = T_COLS / (THREADS * 4);    // 8 float4 per thread per row
static constexpr int GRID = 456;                      // 152 SMs x 3 resident blocks

// Scratch (no cudaMalloc). Zero at process start; RESET by the last block
// each run so graph replays are deterministic.
__device__ unsigned long long g_acc_bits;   // double accumulator, as bits
__device__ unsigned int g_ticket;

__device__ __forceinline__ void load_row(float4 (&v)[VEC],
                                         const float* __restrict__ in,
                                         int row, int tid) {
    const float4* rp = reinterpret_cast<const float4*>(in + (size_t)row * T_COLS);
#pragma unroll
    for (int k = 0; k < VEC; k++) v[k] = rp[tid + k * THREADS];
}

// Per-row reduction + sparse-target loss, ONE __syncthreads total.
// ph selects the s_red ping-pong buffer (alternates with the row buffer),
// which removes the trailing reuse barrier; only tid 0 consumes the sum,
// which removes the broadcast barrier.
__device__ __forceinline__ void compute_row(const float4 (&v)[VEC],
                                            const float* __restrict__ in,
                                            const float* __restrict__ label,
                                            int row, int tid, int ph,
                                            float (*s_red)[WPB],
                                            double* acc) {
    const int wid  = tid >> 5;
    const int lane = tid & 31;

    // Thread-local max consumes ALL of v -> forces the front-batched wait on
    // the full 8xLDG.128 batch (the MLP pattern that saturates HBM).
    float m = -INFINITY;
#pragma unroll
    for (int k = 0; k < VEC; k++)
        m = fmaxf(m, fmaxf(fmaxf(v[k].x, v[k].y), fmaxf(v[k].z, v[k].w)));

    // exp(m) * sum(exp(x-m)) == sum(exp(x)); |x| <~ 6 so fp32-safe
    // (validated: identical rel_err=1.0027e-7 across all prior rounds).
    float cs = 0.0f;
#pragma unroll
    for (int k = 0; k < VEC; k++) {
        cs += __expf(v[k].x - m);
        cs += __expf(v[k].y - m);
        cs += __expf(v[k].z - m);
        cs += __expf(v[k].w - m);
    }
    float s = __expf(m) * cs;

#pragma unroll
    for (int off = 16; off > 0; off >>= 1)
        s += __shfl_xor_sync(0xFFFFFFFFu, s, off);
    if (lane == 0) s_red[ph][wid] = s;
    __syncthreads();                      // the ONLY barrier in the hot path

    if (tid == 0) {
        float tot = 0.0f;
#pragma unroll
        for (int w = 0; w < WPB; w++) tot += s_red[ph][w];
        const float lse = __logf(tot);

        const float pos = label[row] * (float)T_COLS - 1.0f;
        const int fl = (int)floorf(pos);
        const int ce = (int)ceilf(pos);

        // Replicate reference write ORDER (later writes overwrite earlier).
        int   cols[4];
        float vals[4];
        cols[0] = max(fl - 1, 0);          vals[0] = 0.1f;
        cols[1] = fl;                      vals[1] = (fl >= 1) ? 0.4f : 0.5f;
        cols[2] = min(ce + 1, T_COLS - 1); vals[2] = 0.1f;
        cols[3] = ce;                      vals[3] = (ce < T_COLS - 1) ? 0.4f : 0.5f;

        float wsum = 0.0f, dot = 0.0f;
#pragma unroll
        for (int i = 0; i < 4; i++) {
            bool alive = true;
#pragma unroll
            for (int j = i + 1; j < 4; j++)
                if (cols[j] == cols[i]) alive = false;   // last write wins
            if (alive) {
                const float x = in[(size_t)row * T_COLS + cols[i]];  // L1/L2-hot
                wsum += vals[i];
                dot  += vals[i] * x;
            }
        }
        *acc += (double)(wsum * lse - dot);
        // Meanwhile the other 7 warps are already issuing the next row's loads.
    }
}

// 3 blocks/SM cap: two row buffers (64 regs) + scalars fit in <=85 regs; the
// explicit one-row-ahead load pipeline hides DRAM latency, not occupancy.
__global__ __launch_bounds__(THREADS, 3)
void loss_kernel(const float* __restrict__ in,
                 const float* __restrict__ label,
                 float* __restrict__ out) {
    __shared__ float s_red[2][WPB];       // ping-pong: no trailing barrier

    const int tid = threadIdx.x;
    const int bid = blockIdx.x;

    double acc = 0.0;                     // meaningful on tid 0 only
    float4 a[VEC], b[VEC];

    // Software pipeline over this block's rows: bid, bid+GRID, ...
    // The NEXT row's loads are issued before the current row is consumed,
    // so each block always has a full 32KB row in flight.
    int r0 = bid;
    load_row(a, in, r0, tid);             // GRID < N_ROWS: always valid
    while (r0 < N_ROWS) {
        const int r1 = r0 + GRID;
        if (r1 < N_ROWS) load_row(b, in, r1, tid);
        compute_row(a, in, label, r0, tid, 0, s_red, &acc);
        if (r1 < N_ROWS) {
            const int r2 = r1 + GRID;
            if (r2 < N_ROWS) load_row(a, in, r2, tid);
            compute_row(b, in, label, r1, tid, 1, s_red, &acc);
        }
        r0 = r1 + GRID;
    }

    // Per-block result -> global double atomic; last block finalizes.
    if (tid == 0) {
        atomicAdd(reinterpret_cast<double*>(&g_acc_bits), acc);
        __threadfence();
        const unsigned t = atomicAdd(&g_ticket, 1u);
        if (t == (unsigned)(GRID - 1)) {
            g_ticket = 0;                                    // reset for replay
            const unsigned long long bits = atomicExch(&g_acc_bits, 0ull);
            const double total = __longlong_as_double((long long)bits);
            out[0] = (float)(total / (double)N_ROWS);
        }
    }
}

extern "C" void kernel_launch(void* const* d_in, const int* in_sizes, int n_in,
                              void* d_out, int out_size) {
    const float* input = (const float*)d_in[0];   // [N, T] fp32
    const float* label = (const float*)d_in[1];   // [N] fp32
    float* out = (float*)d_out;

    loss_kernel<<<GRID, THREADS>>>(input, label, out);
}